// round 14
// baseline (speedup 1.0000x reference)
#include <cuda_runtime.h>
#include <cuda_fp16.h>

#define NUM_B 2
#define NUM_H 32
#define SEQ   2048
#define HD    128
#define BM    128
#define BN    64
#define NTHREADS 256
#define NTILES (SEQ/BN)          // 32 key tiles per (b,h)

// K fp16 permuted layout: [key][perm(dim)], row stride 144 halves (288 B)
#define KHSTR 144
#define KHIMG (BN*KHSTR)         // 9216 halves
#define KBYTES (KHIMG*2)         // 18432

// V fp16 permuted layout: [dim][perm(key)], row stride 80 halves (160 B)
#define VHSTR 80
#define VHIMG (HD*VHSTR)         // 10240 halves
#define VBYTES (VHIMG*2)         // 20480

#define SMEM_BYTES (2*KBYTES + 2*VBYTES)   // 77824

// prep smem: raw K + raw V tiles, row stride 132 floats
#define PSR 132
#define PREP_SMEM_BYTES (2*BN*PSR*4)

// Pre-packed fp16 K,V scratch (device globals: allocation-free)
__device__ __half g_K2[(size_t)NUM_B*NUM_H*NTILES*KHIMG];   // ~37.7 MB
__device__ __half g_V2[(size_t)NUM_B*NUM_H*NTILES*VHIMG];   // ~41.9 MB

__device__ __forceinline__ float ex2f(float x){
    float r; asm("ex2.approx.f32 %0, %1;" : "=f"(r) : "f"(x)); return r;
}
__device__ __forceinline__ unsigned packh2(float a, float b){
    __half2 h = __float22half2_rn(make_float2(a, b));
    return *(unsigned*)&h;
}
__device__ __forceinline__ void mma_f16(float c[4], const unsigned a[4],
                                        unsigned b0, unsigned b1){
    asm volatile("mma.sync.aligned.m16n8k16.row.col.f32.f16.f16.f32 "
                 "{%0,%1,%2,%3},{%4,%5,%6,%7},{%8,%9},{%0,%1,%2,%3};"
                 : "+f"(c[0]),"+f"(c[1]),"+f"(c[2]),"+f"(c[3])
                 : "r"(a[0]),"r"(a[1]),"r"(a[2]),"r"(a[3]),"r"(b0),"r"(b1));
}
__device__ __forceinline__ void mbar_wait(unsigned bar, unsigned parity){
    asm volatile(
        "{\n\t"
        ".reg .pred P1;\n\t"
        "WAIT_%=:\n\t"
        "mbarrier.try_wait.parity.acquire.cta.shared::cta.b64 P1, [%0], %1, 0x989680;\n\t"
        "@P1 bra.uni DONE_%=;\n\t"
        "bra.uni WAIT_%=;\n\t"
        "DONE_%=:\n\t"
        "}"
        :: "r"(bar), "r"(parity) : "memory");
}

// ===== prep: raw fp32 -> fp16 permuted K' and V' (all global I/O coalesced) =====
__global__ void __launch_bounds__(NTHREADS, 1)
prep_kv(const float* __restrict__ K, const float* __restrict__ V)
{
    extern __shared__ float ps[];
    float* sk = ps;                // raw K tile: [64][PSR]
    float* sv = ps + BN*PSR;       // raw V tile: [64][PSR]

    const int tile = blockIdx.x, h = blockIdx.y, b = blockIdx.z;
    const int tid  = threadIdx.x;
    const size_t src = ((size_t)(b*NUM_H + h)*SEQ + (size_t)tile*BN) * HD;
    __half* kd = g_K2 + ((size_t)(b*NUM_H + h)*NTILES + tile) * KHIMG;
    __half* vd = g_V2 + ((size_t)(b*NUM_H + h)*NTILES + tile) * VHIMG;

    const unsigned skb = (unsigned)__cvta_generic_to_shared(sk);
    const unsigned svb = (unsigned)__cvta_generic_to_shared(sv);

    #pragma unroll
    for (int i = 0; i < (BN*HD/4)/NTHREADS; i++){
        int idx = tid + i*NTHREADS;
        int row = idx >> 5;
        int c4  = (idx & 31) * 4;
        asm volatile("cp.async.cg.shared.global [%0], [%1], 16;"
                     :: "r"(skb + (unsigned)((row*PSR + c4)*4)),
                        "l"(K + src + (size_t)row*HD + c4));
        asm volatile("cp.async.cg.shared.global [%0], [%1], 16;"
                     :: "r"(svb + (unsigned)((row*PSR + c4)*4)),
                        "l"(V + src + (size_t)row*HD + c4));
    }
    asm volatile("cp.async.commit_group;");
    asm volatile("cp.async.wait_group 0;");
    __syncthreads();

    // K': [key row][perm(dim)] fp16. Per 16-dim block t, pos(k): {2c0,2c0+1,2c0+8,2c0+9}
    // contiguous at 4c0. Thread writes one uint4 (8 halves) at [row][s*8].
    #pragma unroll
    for (int i = 0; i < 4; i++){
        int idx = tid + i*NTHREADS;          // 0..1023 = 64 rows x 16 subgroups
        int row = idx >> 4;
        int s   = idx & 15;
        int t   = s >> 1;
        int u   = s & 1;
        int kb  = 16*t + 4*u;
        const float* sp = sk + row*PSR;
        uint4 o4;
        o4.x = packh2(sp[kb+0 ], sp[kb+1 ]);
        o4.y = packh2(sp[kb+8 ], sp[kb+9 ]);
        o4.z = packh2(sp[kb+2 ], sp[kb+3 ]);
        o4.w = packh2(sp[kb+10], sp[kb+11]);
        *(uint4*)(kd + row*KHSTR + s*8) = o4;
    }

    // V': [dim][perm(key)] fp16, same 16-block permutation over keys.
    #pragma unroll
    for (int i = 0; i < 4; i++){
        int idx = tid + i*NTHREADS;          // 0..1023 = 128 dims x 8 subgroups
        int dim = idx >> 3;
        int s   = idx & 7;
        int t   = s >> 1;
        int u   = s & 1;
        int kb  = 16*t + 4*u;
        const float* sp = sv + dim;
        uint4 o4;
        o4.x = packh2(sp[(kb+0 )*PSR], sp[(kb+1 )*PSR]);
        o4.y = packh2(sp[(kb+8 )*PSR], sp[(kb+9 )*PSR]);
        o4.z = packh2(sp[(kb+2 )*PSR], sp[(kb+3 )*PSR]);
        o4.w = packh2(sp[(kb+10)*PSR], sp[(kb+11)*PSR]);
        *(uint4*)(vd + dim*VHSTR + s*8) = o4;
    }
}

// ============================ main attention ============================
__global__ void __launch_bounds__(NTHREADS, 1)
fa_fwd(const float* __restrict__ Q, float* __restrict__ Out)
{
    extern __shared__ char smc[];
    __shared__ unsigned long long s_mbar[2];
    __half* Ks = (__half*)smc;                 // 2 x KHIMG halves
    __half* Vs = (__half*)(smc + 2*KBYTES);    // 2 x VHIMG halves

    const int tid  = threadIdx.x;
    const int warp = tid >> 5;
    const int lane = tid & 31;
    const int r0   = lane >> 2;
    const int c0   = lane & 3;

    // heavy-first: largest qb gets earliest block ids
    const int qb = (SEQ/BM - 1) - blockIdx.x;
    const int h = blockIdx.y, b = blockIdx.z;
    const int qbase = qb * BM;
    const size_t bh_off = ((size_t)b*NUM_H + h) * (size_t)SEQ * HD;
    const float* Qp = Q + bh_off;
    const size_t bhT = (size_t)(b*NUM_H + h) * NTILES;

    const unsigned ks_b = (unsigned)__cvta_generic_to_shared(Ks);
    const unsigned vs_b = (unsigned)__cvta_generic_to_shared(Vs);
    const unsigned mb0  = (unsigned)__cvta_generic_to_shared(&s_mbar[0]);
    const unsigned mb1  = (unsigned)__cvta_generic_to_shared(&s_mbar[1]);

    if (tid == 0){
        asm volatile("mbarrier.init.shared.b64 [%0], %1;" :: "r"(mb0), "r"(1) : "memory");
        asm volatile("mbarrier.init.shared.b64 [%0], %1;" :: "r"(mb1), "r"(1) : "memory");
    }
    __syncthreads();

    // 1/sqrt(128) * log2(e): layer-scaling cancels; softmax in exp2 domain
    const float SCALE2 = 0.08838834764831845f * 1.4426950408889634f;

    // ---- Q fragments: fp16 m16n8k16 A layout, pre-scaled, loaded once ----
    unsigned qf[8][4];
    const int qrow0 = qbase + warp*16 + r0;
    const int qrow1 = qrow0 + 8;
    #pragma unroll
    for (int t = 0; t < 8; t++){
        int col = t*16 + 2*c0;
        const float* q0 = Qp + (size_t)qrow0*HD + col;
        const float* q1 = Qp + (size_t)qrow1*HD + col;
        qf[t][0] = packh2(q0[0]*SCALE2, q0[1]*SCALE2);
        qf[t][1] = packh2(q1[0]*SCALE2, q1[1]*SCALE2);
        qf[t][2] = packh2(q0[8]*SCALE2, q0[9]*SCALE2);
        qf[t][3] = packh2(q1[8]*SCALE2, q1[9]*SCALE2);
    }

    float o[16][4];
    #pragma unroll
    for (int i = 0; i < 16; i++){ o[i][0]=0.f; o[i][1]=0.f; o[i][2]=0.f; o[i][3]=0.f; }
    float m0 = -1e30f, m1 = -1e30f, l0 = 0.f, l1 = 0.f;

    const int jmax = 2*qb + 1;

    // single-thread bulk-copy producer (DMA)
    auto load_tiles = [&](int j, int buf){
        if (tid == 0){
            unsigned bar = buf ? mb1 : mb0;
            const __half* kg = g_K2 + (bhT + j)*KHIMG;
            const __half* vg = g_V2 + (bhT + j)*VHIMG;
            asm volatile("mbarrier.arrive.expect_tx.shared.b64 _, [%0], %1;"
                         :: "r"(bar), "r"(KBYTES + VBYTES) : "memory");
            asm volatile("cp.async.bulk.shared::cluster.global.mbarrier::complete_tx::bytes "
                         "[%0], [%1], %2, [%3];"
                         :: "r"(ks_b + (unsigned)(buf*KBYTES)), "l"(kg), "r"(KBYTES), "r"(bar)
                         : "memory");
            asm volatile("cp.async.bulk.shared::cluster.global.mbarrier::complete_tx::bytes "
                         "[%0], [%1], %2, [%3];"
                         :: "r"(vs_b + (unsigned)(buf*VBYTES)), "l"(vg), "r"(VBYTES), "r"(bar)
                         : "memory");
        }
    };

    load_tiles(0, 0);

    for (int j = 0; j <= jmax; j++){
        const int cur = j & 1;
        mbar_wait(cur ? mb1 : mb0, (j >> 1) & 1);   // tile j landed (acquire)
        __syncthreads();                             // all warps done with tile j-1
        if (j < jmax) load_tiles(j + 1, cur ^ 1);

        const __half* Kb = Ks + cur*KHIMG;
        const __half* Vb = Vs + cur*VHIMG;

        // ===== S = Q*K^T (fp16 m16n8k16): one LDS.64 per B-fragment =====
        float sacc[8][4];
        #pragma unroll
        for (int i = 0; i < 8; i++){ sacc[i][0]=0.f; sacc[i][1]=0.f; sacc[i][2]=0.f; sacc[i][3]=0.f; }

        #pragma unroll
        for (int nt = 0; nt < 8; nt++){
            const uint2* kp = (const uint2*)(Kb + (8*nt + r0)*KHSTR + c0*4);
            uint2 kf[8];
            #pragma unroll
            for (int t = 0; t < 8; t++) kf[t] = kp[t*4];   // +t*16 halves
            #pragma unroll
            for (int t = 0; t < 8; t++)
                mma_f16(sacc[nt], qf[t], kf[t].x, kf[t].y);
        }

        // ===== causal mask (diagonal pair only) + row max =====
        const bool maskblk = (j*BN + BN) > qbase;
        float rmax0 = -1e30f, rmax1 = -1e30f;
        #pragma unroll
        for (int nt = 0; nt < 8; nt++){
            if (maskblk){
                int colb = j*BN + nt*8 + 2*c0;
                if (colb     > qrow0) sacc[nt][0] = -1e30f;
                if (colb + 1 > qrow0) sacc[nt][1] = -1e30f;
                if (colb     > qrow1) sacc[nt][2] = -1e30f;
                if (colb + 1 > qrow1) sacc[nt][3] = -1e30f;
            }
            rmax0 = fmaxf(rmax0, fmaxf(sacc[nt][0], sacc[nt][1]));
            rmax1 = fmaxf(rmax1, fmaxf(sacc[nt][2], sacc[nt][3]));
        }
        rmax0 = fmaxf(rmax0, __shfl_xor_sync(0xffffffffu, rmax0, 1));
        rmax0 = fmaxf(rmax0, __shfl_xor_sync(0xffffffffu, rmax0, 2));
        rmax1 = fmaxf(rmax1, __shfl_xor_sync(0xffffffffu, rmax1, 1));
        rmax1 = fmaxf(rmax1, __shfl_xor_sync(0xffffffffu, rmax1, 2));

        float m0n = fmaxf(m0, rmax0), m1n = fmaxf(m1, rmax1);
        float al0 = ex2f(m0 - m0n), al1 = ex2f(m1 - m1n);
        m0 = m0n; m1 = m1n;

        // ===== P = exp2(S - m) + row sums; pack straight into fp16 A-fragments =====
        unsigned pa[4][4];
        float rs0 = 0.f, rs1 = 0.f;
        #pragma unroll
        for (int t = 0; t < 4; t++){
            float p0 = ex2f(sacc[2*t][0] - m0n);
            float p1 = ex2f(sacc[2*t][1] - m0n);
            float p2 = ex2f(sacc[2*t][2] - m1n);
            float p3 = ex2f(sacc[2*t][3] - m1n);
            float p4 = ex2f(sacc[2*t+1][0] - m0n);
            float p5 = ex2f(sacc[2*t+1][1] - m0n);
            float p6 = ex2f(sacc[2*t+1][2] - m1n);
            float p7 = ex2f(sacc[2*t+1][3] - m1n);
            rs0 += (p0 + p1) + (p4 + p5);
            rs1 += (p2 + p3) + (p6 + p7);
            pa[t][0] = packh2(p0, p1);
            pa[t][1] = packh2(p2, p3);
            pa[t][2] = packh2(p4, p5);
            pa[t][3] = packh2(p6, p7);
        }
        rs0 += __shfl_xor_sync(0xffffffffu, rs0, 1);
        rs0 += __shfl_xor_sync(0xffffffffu, rs0, 2);
        rs1 += __shfl_xor_sync(0xffffffffu, rs1, 1);
        rs1 += __shfl_xor_sync(0xffffffffu, rs1, 2);
        l0 = l0*al0 + rs0;
        l1 = l1*al1 + rs1;

        #pragma unroll
        for (int nt = 0; nt < 16; nt++){
            o[nt][0] *= al0; o[nt][1] *= al0; o[nt][2] *= al1; o[nt][3] *= al1;
        }

        // ===== O += P*V (fp16 m16n8k16): one LDS.64 per B-fragment =====
        #pragma unroll
        for (int nt = 0; nt < 16; nt++){
            const uint2* vp = (const uint2*)(Vb + (8*nt + r0)*VHSTR + c0*4);
            uint2 vf[4];
            #pragma unroll
            for (int t = 0; t < 4; t++) vf[t] = vp[t*4];   // +t*16 halves
            #pragma unroll
            for (int t = 0; t < 4; t++)
                mma_f16(o[nt], pa[t], vf[t].x, vf[t].y);
        }
        // no end barrier: next iter's wait+sync licenses buffer reuse
    }

    // ===== epilogue: normalize + write [b, q, h*D] =====
    float inv0 = 1.f / l0, inv1 = 1.f / l1;
    const size_t ob = (size_t)b * SEQ * NUM_H * HD + (size_t)h * HD;
    #pragma unroll
    for (int nt = 0; nt < 16; nt++){
        int col = nt*8 + 2*c0;
        *(float2*)&Out[ob + (size_t)qrow0 * NUM_H * HD + col] =
            make_float2(o[nt][0]*inv0, o[nt][1]*inv0);
        *(float2*)&Out[ob + (size_t)qrow1 * NUM_H * HD + col] =
            make_float2(o[nt][2]*inv1, o[nt][3]*inv1);
    }
}

extern "C" void kernel_launch(void* const* d_in, const int* in_sizes, int n_in,
                              void* d_out, int out_size)
{
    const float* Q = (const float*)d_in[0];
    const float* K = (const float*)d_in[1];
    const float* V = (const float*)d_in[2];
    float* Out = (float*)d_out;

    cudaFuncSetAttribute(fa_fwd, cudaFuncAttributeMaxDynamicSharedMemorySize, SMEM_BYTES);
    cudaFuncSetAttribute(prep_kv, cudaFuncAttributeMaxDynamicSharedMemorySize, PREP_SMEM_BYTES);

    dim3 pgrid(NTILES, NUM_H, NUM_B);
    prep_kv<<<pgrid, NTHREADS, PREP_SMEM_BYTES>>>(K, V);

    dim3 grid(SEQ / BM, NUM_H, NUM_B);
    fa_fwd<<<grid, NTHREADS, SMEM_BYTES>>>(Q, Out);
}

// round 16
// speedup vs baseline: 1.1174x; 1.1174x over previous
#include <cuda_runtime.h>
#include <cuda_fp16.h>

#define NUM_B 2
#define NUM_H 32
#define SEQ   2048
#define HD    128
#define BM    64                 // q rows per CTA (4 warps x 16)
#define BN    64
#define NTHREADS 128
#define PREP_T   256
#define NTILES (SEQ/BN)          // 32 key tiles per (b,h)

// K fp16 permuted layout: [key][perm(dim)], row stride 144 halves (288 B)
#define KHSTR 144
#define KHIMG (BN*KHSTR)         // 9216 halves
#define KBYTES (KHIMG*2)         // 18432

// V fp16 permuted layout: [dim][perm(key)], row stride 80 halves (160 B)
#define VHSTR 80
#define VHIMG (HD*VHSTR)         // 10240 halves
#define VBYTES (VHIMG*2)         // 20480

#define SMEM_BYTES (2*KBYTES + 2*VBYTES)   // 77824 -> 2 CTAs/SM

// prep smem: raw K + raw V tiles, row stride 132 floats
#define PSR 132
#define PREP_SMEM_BYTES (2*BN*PSR*4)

// Pre-packed fp16 K,V scratch (device globals: allocation-free)
__device__ __half g_K2[(size_t)NUM_B*NUM_H*NTILES*KHIMG];   // ~37.7 MB
__device__ __half g_V2[(size_t)NUM_B*NUM_H*NTILES*VHIMG];   // ~41.9 MB

__device__ __forceinline__ float ex2f(float x){
    float r; asm("ex2.approx.f32 %0, %1;" : "=f"(r) : "f"(x)); return r;
}
__device__ __forceinline__ unsigned packh2(float a, float b){
    __half2 h = __float22half2_rn(make_float2(a, b));
    return *(unsigned*)&h;
}
__device__ __forceinline__ void mma_f16(float c[4], const unsigned a[4],
                                        unsigned b0, unsigned b1){
    asm volatile("mma.sync.aligned.m16n8k16.row.col.f32.f16.f16.f32 "
                 "{%0,%1,%2,%3},{%4,%5,%6,%7},{%8,%9},{%0,%1,%2,%3};"
                 : "+f"(c[0]),"+f"(c[1]),"+f"(c[2]),"+f"(c[3])
                 : "r"(a[0]),"r"(a[1]),"r"(a[2]),"r"(a[3]),"r"(b0),"r"(b1));
}
__device__ __forceinline__ void mbar_wait(unsigned bar, unsigned parity){
    asm volatile(
        "{\n\t"
        ".reg .pred P1;\n\t"
        "W_%=:\n\t"
        "mbarrier.try_wait.parity.acquire.cta.shared::cta.b64 P1, [%0], %1, 0x989680;\n\t"
        "@P1 bra.uni D_%=;\n\t"
        "bra.uni W_%=;\n\t"
        "D_%=:\n\t"
        "}"
        :: "r"(bar), "r"(parity) : "memory");
}

// ===== prep: raw fp32 -> fp16 permuted K' and V' (all global I/O coalesced) =====
__global__ void __launch_bounds__(PREP_T, 1)
prep_kv(const float* __restrict__ K, const float* __restrict__ V)
{
    extern __shared__ float ps[];
    float* sk = ps;                // raw K tile: [64][PSR]
    float* sv = ps + BN*PSR;       // raw V tile: [64][PSR]

    const int tile = blockIdx.x, h = blockIdx.y, b = blockIdx.z;
    const int tid  = threadIdx.x;
    const size_t src = ((size_t)(b*NUM_H + h)*SEQ + (size_t)tile*BN) * HD;
    __half* kd = g_K2 + ((size_t)(b*NUM_H + h)*NTILES + tile) * KHIMG;
    __half* vd = g_V2 + ((size_t)(b*NUM_H + h)*NTILES + tile) * VHIMG;

    const unsigned skb = (unsigned)__cvta_generic_to_shared(sk);
    const unsigned svb = (unsigned)__cvta_generic_to_shared(sv);

    #pragma unroll
    for (int i = 0; i < (BN*HD/4)/PREP_T; i++){
        int idx = tid + i*PREP_T;
        int row = idx >> 5;
        int c4  = (idx & 31) * 4;
        asm volatile("cp.async.cg.shared.global [%0], [%1], 16;"
                     :: "r"(skb + (unsigned)((row*PSR + c4)*4)),
                        "l"(K + src + (size_t)row*HD + c4));
        asm volatile("cp.async.cg.shared.global [%0], [%1], 16;"
                     :: "r"(svb + (unsigned)((row*PSR + c4)*4)),
                        "l"(V + src + (size_t)row*HD + c4));
    }
    asm volatile("cp.async.commit_group;");
    asm volatile("cp.async.wait_group 0;");
    __syncthreads();

    // K': [key row][perm(dim)] fp16; per 16-dim block t, {2c0,2c0+1,2c0+8,2c0+9} contiguous
    #pragma unroll
    for (int i = 0; i < 4; i++){
        int idx = tid + i*PREP_T;            // 0..1023 = 64 rows x 16 subgroups
        int row = idx >> 4;
        int s   = idx & 15;
        int t   = s >> 1;
        int u   = s & 1;
        int kb  = 16*t + 4*u;
        const float* sp = sk + row*PSR;
        uint4 o4;
        o4.x = packh2(sp[kb+0 ], sp[kb+1 ]);
        o4.y = packh2(sp[kb+8 ], sp[kb+9 ]);
        o4.z = packh2(sp[kb+2 ], sp[kb+3 ]);
        o4.w = packh2(sp[kb+10], sp[kb+11]);
        *(uint4*)(kd + row*KHSTR + s*8) = o4;
    }

    // V': [dim][perm(key)] fp16, same 16-block permutation over keys
    #pragma unroll
    for (int i = 0; i < 4; i++){
        int idx = tid + i*PREP_T;            // 0..1023 = 128 dims x 8 subgroups
        int dim = idx >> 3;
        int s   = idx & 7;
        int t   = s >> 1;
        int u   = s & 1;
        int kb  = 16*t + 4*u;
        const float* sp = sv + dim;
        uint4 o4;
        o4.x = packh2(sp[(kb+0 )*PSR], sp[(kb+1 )*PSR]);
        o4.y = packh2(sp[(kb+8 )*PSR], sp[(kb+9 )*PSR]);
        o4.z = packh2(sp[(kb+2 )*PSR], sp[(kb+3 )*PSR]);
        o4.w = packh2(sp[(kb+10)*PSR], sp[(kb+11)*PSR]);
        *(uint4*)(vd + dim*VHSTR + s*8) = o4;
    }
}

// ============================ main attention ============================
__global__ void __launch_bounds__(NTHREADS, 2)
fa_fwd(const float* __restrict__ Q, float* __restrict__ Out)
{
    extern __shared__ char smc[];
    __shared__ unsigned long long s_mbar[2];
    __half* Ks = (__half*)smc;                 // 2 x KHIMG halves
    __half* Vs = (__half*)(smc + 2*KBYTES);    // 2 x VHIMG halves

    const int tid  = threadIdx.x;
    const int warp = tid >> 5;                 // 0..3
    const int lane = tid & 31;
    const int r0   = lane >> 2;
    const int c0   = lane & 3;

    // heavy-first: largest qb gets earliest block ids
    const int qb = (SEQ/BM - 1) - blockIdx.x;  // 0..31
    const int h = blockIdx.y, b = blockIdx.z;
    const int qbase = qb * BM;
    const size_t bh_off = ((size_t)b*NUM_H + h) * (size_t)SEQ * HD;
    const float* Qp = Q + bh_off;
    const size_t bhT = (size_t)(b*NUM_H + h) * NTILES;

    const unsigned ks_b = (unsigned)__cvta_generic_to_shared(Ks);
    const unsigned vs_b = (unsigned)__cvta_generic_to_shared(Vs);
    const unsigned mb0  = (unsigned)__cvta_generic_to_shared(&s_mbar[0]);
    const unsigned mb1  = (unsigned)__cvta_generic_to_shared(&s_mbar[1]);

    if (tid == 0){
        asm volatile("mbarrier.init.shared.b64 [%0], %1;" :: "r"(mb0), "r"(1) : "memory");
        asm volatile("mbarrier.init.shared.b64 [%0], %1;" :: "r"(mb1), "r"(1) : "memory");
    }
    __syncthreads();

    // 1/sqrt(128) * log2(e): layer-scaling cancels; softmax in exp2 domain
    const float SCALE2 = 0.08838834764831845f * 1.4426950408889634f;

    // ---- Q fragments: fp16 m16n8k16 A layout, pre-scaled, loaded once ----
    unsigned qf[8][4];
    const int qrow0 = qbase + warp*16 + r0;
    const int qrow1 = qrow0 + 8;
    #pragma unroll
    for (int t = 0; t < 8; t++){
        int col = t*16 + 2*c0;
        const float* q0 = Qp + (size_t)qrow0*HD + col;
        const float* q1 = Qp + (size_t)qrow1*HD + col;
        qf[t][0] = packh2(q0[0]*SCALE2, q0[1]*SCALE2);
        qf[t][1] = packh2(q1[0]*SCALE2, q1[1]*SCALE2);
        qf[t][2] = packh2(q0[8]*SCALE2, q0[9]*SCALE2);
        qf[t][3] = packh2(q1[8]*SCALE2, q1[9]*SCALE2);
    }

    float o[16][4];
    #pragma unroll
    for (int i = 0; i < 16; i++){ o[i][0]=0.f; o[i][1]=0.f; o[i][2]=0.f; o[i][3]=0.f; }
    float m0 = -1e30f, m1 = -1e30f, l0 = 0.f, l1 = 0.f;

    const int jmax = qb;      // causal at 64-row granularity: key tiles 0..qb

    // single-thread bulk-copy producer (DMA)
    auto load_tiles = [&](int j, int buf){
        if (tid == 0){
            unsigned bar = buf ? mb1 : mb0;
            const __half* kg = g_K2 + (bhT + j)*KHIMG;
            const __half* vg = g_V2 + (bhT + j)*VHIMG;
            asm volatile("mbarrier.arrive.expect_tx.shared.b64 _, [%0], %1;"
                         :: "r"(bar), "r"(KBYTES + VBYTES) : "memory");
            asm volatile("cp.async.bulk.shared::cluster.global.mbarrier::complete_tx::bytes "
                         "[%0], [%1], %2, [%3];"
                         :: "r"(ks_b + (unsigned)(buf*KBYTES)), "l"(kg), "r"(KBYTES), "r"(bar)
                         : "memory");
            asm volatile("cp.async.bulk.shared::cluster.global.mbarrier::complete_tx::bytes "
                         "[%0], [%1], %2, [%3];"
                         :: "r"(vs_b + (unsigned)(buf*VBYTES)), "l"(vg), "r"(VBYTES), "r"(bar)
                         : "memory");
        }
    };

    load_tiles(0, 0);

    for (int j = 0; j <= jmax; j++){
        const int cur = j & 1;
        mbar_wait(cur ? mb1 : mb0, (j >> 1) & 1);   // tile j landed (acquire)
        __syncthreads();                             // all warps done with tile j-1
        if (j < jmax) load_tiles(j + 1, cur ^ 1);

        const __half* Kb = Ks + cur*KHIMG;
        const __half* Vb = Vs + cur*VHIMG;

        // ===== S = Q*K^T (fp16 m16n8k16): one LDS.64 per B-fragment =====
        float sacc[8][4];
        #pragma unroll
        for (int i = 0; i < 8; i++){ sacc[i][0]=0.f; sacc[i][1]=0.f; sacc[i][2]=0.f; sacc[i][3]=0.f; }

        #pragma unroll
        for (int nt = 0; nt < 8; nt++){
            const uint2* kp = (const uint2*)(Kb + (8*nt + r0)*KHSTR + c0*4);
            uint2 kf[8];
            #pragma unroll
            for (int t = 0; t < 8; t++) kf[t] = kp[t*4];   // +t*16 halves
            #pragma unroll
            for (int t = 0; t < 8; t++)
                mma_f16(sacc[nt], qf[t], kf[t].x, kf[t].y);
        }

        // ===== causal mask (diagonal tile only) + row max =====
        const bool maskblk = (j == jmax);   // only diagonal tile needs masking
        float rmax0 = -1e30f, rmax1 = -1e30f;
        #pragma unroll
        for (int nt = 0; nt < 8; nt++){
            if (maskblk){
                int colb = j*BN + nt*8 + 2*c0;
                if (colb     > qrow0) sacc[nt][0] = -1e30f;
                if (colb + 1 > qrow0) sacc[nt][1] = -1e30f;
                if (colb     > qrow1) sacc[nt][2] = -1e30f;
                if (colb + 1 > qrow1) sacc[nt][3] = -1e30f;
            }
            rmax0 = fmaxf(rmax0, fmaxf(sacc[nt][0], sacc[nt][1]));
            rmax1 = fmaxf(rmax1, fmaxf(sacc[nt][2], sacc[nt][3]));
        }
        rmax0 = fmaxf(rmax0, __shfl_xor_sync(0xffffffffu, rmax0, 1));
        rmax0 = fmaxf(rmax0, __shfl_xor_sync(0xffffffffu, rmax0, 2));
        rmax1 = fmaxf(rmax1, __shfl_xor_sync(0xffffffffu, rmax1, 1));
        rmax1 = fmaxf(rmax1, __shfl_xor_sync(0xffffffffu, rmax1, 2));

        float m0n = fmaxf(m0, rmax0), m1n = fmaxf(m1, rmax1);
        float al0 = ex2f(m0 - m0n), al1 = ex2f(m1 - m1n);
        m0 = m0n; m1 = m1n;

        // ===== P = exp2(S - m) + row sums; pack straight into fp16 A-fragments =====
        unsigned pa[4][4];
        float rs0 = 0.f, rs1 = 0.f;
        #pragma unroll
        for (int t = 0; t < 4; t++){
            float p0 = ex2f(sacc[2*t][0] - m0n);
            float p1 = ex2f(sacc[2*t][1] - m0n);
            float p2 = ex2f(sacc[2*t][2] - m1n);
            float p3 = ex2f(sacc[2*t][3] - m1n);
            float p4 = ex2f(sacc[2*t+1][0] - m0n);
            float p5 = ex2f(sacc[2*t+1][1] - m0n);
            float p6 = ex2f(sacc[2*t+1][2] - m1n);
            float p7 = ex2f(sacc[2*t+1][3] - m1n);
            rs0 += (p0 + p1) + (p4 + p5);
            rs1 += (p2 + p3) + (p6 + p7);
            pa[t][0] = packh2(p0, p1);
            pa[t][1] = packh2(p2, p3);
            pa[t][2] = packh2(p4, p5);
            pa[t][3] = packh2(p6, p7);
        }
        rs0 += __shfl_xor_sync(0xffffffffu, rs0, 1);
        rs0 += __shfl_xor_sync(0xffffffffu, rs0, 2);
        rs1 += __shfl_xor_sync(0xffffffffu, rs1, 1);
        rs1 += __shfl_xor_sync(0xffffffffu, rs1, 2);
        l0 = l0*al0 + rs0;
        l1 = l1*al1 + rs1;

        #pragma unroll
        for (int nt = 0; nt < 16; nt++){
            o[nt][0] *= al0; o[nt][1] *= al0; o[nt][2] *= al1; o[nt][3] *= al1;
        }

        // ===== O += P*V (fp16 m16n8k16): one LDS.64 per B-fragment =====
        #pragma unroll
        for (int nt = 0; nt < 16; nt++){
            const uint2* vp = (const uint2*)(Vb + (8*nt + r0)*VHSTR + c0*4);
            uint2 vf[4];
            #pragma unroll
            for (int t = 0; t < 4; t++) vf[t] = vp[t*4];   // +t*16 halves
            #pragma unroll
            for (int t = 0; t < 4; t++)
                mma_f16(o[nt], pa[t], vf[t].x, vf[t].y);
        }
        // no end barrier: next iter's wait+sync licenses buffer reuse
    }

    // ===== epilogue: normalize + write [b, q, h*D] =====
    float inv0 = 1.f / l0, inv1 = 1.f / l1;
    const size_t ob = (size_t)b * SEQ * NUM_H * HD + (size_t)h * HD;
    #pragma unroll
    for (int nt = 0; nt < 16; nt++){
        int col = nt*8 + 2*c0;
        *(float2*)&Out[ob + (size_t)qrow0 * NUM_H * HD + col] =
            make_float2(o[nt][0]*inv0, o[nt][1]*inv0);
        *(float2*)&Out[ob + (size_t)qrow1 * NUM_H * HD + col] =
            make_float2(o[nt][2]*inv1, o[nt][3]*inv1);
    }
}

extern "C" void kernel_launch(void* const* d_in, const int* in_sizes, int n_in,
                              void* d_out, int out_size)
{
    const float* Q = (const float*)d_in[0];
    const float* K = (const float*)d_in[1];
    const float* V = (const float*)d_in[2];
    float* Out = (float*)d_out;

    cudaFuncSetAttribute(fa_fwd, cudaFuncAttributeMaxDynamicSharedMemorySize, SMEM_BYTES);
    cudaFuncSetAttribute(prep_kv, cudaFuncAttributeMaxDynamicSharedMemorySize, PREP_SMEM_BYTES);

    dim3 pgrid(NTILES, NUM_H, NUM_B);
    prep_kv<<<pgrid, PREP_T, PREP_SMEM_BYTES>>>(K, V);

    dim3 grid(SEQ / BM, NUM_H, NUM_B);
    fa_fwd<<<grid, NTHREADS, SMEM_BYTES>>>(Q, Out);
}